// round 14
// baseline (speedup 1.0000x reference)
#include <cuda_runtime.h>
#include <math.h>

constexpr int Tt  = 2048;
constexpr int DHd = 512;
constexpr int NT  = 8 * 2048;
constexpr float SCALE = 0.044194173824159216f; // 512^-0.5

__device__ float g_q [NT * DHd];
__device__ float g_k [NT * DHd];
__device__ float g_v [NT * DHd];
__device__ float g_g [NT * DHd];
__device__ float g_Qc[NT * DHd];
__device__ float g_Qr[NT * DHd];
__device__ float g_Kr[NT * DHd];
__device__ float g_Qg[NT * DHd];
__device__ float g_Kg[NT * DHd];
__device__ float g_M [DHd * DHd];
__device__ float g_hist[8 * 32 * DHd];
__device__ float g_W [8 * 64 * 32];
__device__ float g_cos[Tt * 256];
__device__ float g_sin[Tt * 256];

// ---------------- GEMM (unchanged, ~88% of fp32 FFMA ceiling) ----------------
template<int MODE, int TRANSB, int SEL>
__global__ void gemm64(const float* __restrict__ Ain,
                       const float* __restrict__ Bin,
                       const float* __restrict__ bias) {
    const float* A;
    float* C;
    if constexpr (SEL == 0)      { A = Ain;  C = g_q;  }
    else if constexpr (SEL == 1) { A = Ain;  C = g_k;  }
    else if constexpr (SEL == 2) { A = Ain;  C = g_v;  }
    else if constexpr (SEL == 3) { A = Ain;  C = g_g;  }
    else if constexpr (SEL == 4) { A = g_Qr; C = g_Qg; }
    else                         { A = g_Kr; C = g_Kg; }
    const float* Bm = (SEL >= 4) ? (const float*)g_M : Bin;

    constexpr int K = 512, N = 512;
    __shared__ float As[16][68];
    __shared__ float Bs[16][68];
    const int t  = threadIdx.x;
    const int tx = t & 15, ty = t >> 4;
    const int n0 = blockIdx.x * 64, m0 = blockIdx.y * 64;
    const int ar = t >> 2, ac = (t & 3) << 2;
    float acc[4][4] = {};

    for (int k0 = 0; k0 < K; k0 += 16) {
        float4 va = *(const float4*)&A[(size_t)(m0 + ar) * K + k0 + ac];
        As[ac + 0][ar] = va.x; As[ac + 1][ar] = va.y;
        As[ac + 2][ar] = va.z; As[ac + 3][ar] = va.w;
        if constexpr (TRANSB) {
            float4 vb = *(const float4*)&Bm[(size_t)(n0 + ar) * K + k0 + ac];
            Bs[ac + 0][ar] = vb.x; Bs[ac + 1][ar] = vb.y;
            Bs[ac + 2][ar] = vb.z; Bs[ac + 3][ar] = vb.w;
        } else {
            *(float4*)&Bs[ty][tx << 2] =
                *(const float4*)&Bm[(size_t)(k0 + ty) * N + n0 + (tx << 2)];
        }
        __syncthreads();
        #pragma unroll
        for (int kk = 0; kk < 16; kk++) {
            float4 a4 = *(const float4*)&As[kk][ty << 2];
            float4 b4 = *(const float4*)&Bs[kk][tx << 2];
            float av[4] = {a4.x, a4.y, a4.z, a4.w};
            float bv[4] = {b4.x, b4.y, b4.z, b4.w};
            #pragma unroll
            for (int i = 0; i < 4; i++)
                #pragma unroll
                for (int j = 0; j < 4; j++)
                    acc[i][j] += av[i] * bv[j];
        }
        __syncthreads();
    }
    #pragma unroll
    for (int i = 0; i < 4; i++) {
        size_t rowb = (size_t)(m0 + (ty << 2) + i) * N;
        #pragma unroll
        for (int j = 0; j < 4; j++) {
            int n = n0 + (tx << 2) + j;
            float v = acc[i][j];
            if constexpr (MODE == 1) v = 1.f / (1.f + __expf(-(v + bias[n])));
            C[rowb + n] = v;
        }
    }
}

__global__ void rope_table() {
    int tp = blockIdx.x, p = threadIdx.x;
    double invf = pow(10000.0, -((double)(2 * p)) / 512.0);
    float ang = (float)tp * (float)invf;
    g_cos[tp * 256 + p] = (float)cos((double)ang);
    g_sin[tp * 256 + p] = (float)sin((double)ang);
}

__global__ void build_M(const float* __restrict__ A) {
    int idx = blockIdx.x * 256 + threadIdx.x;
    int d = idx >> 9, e = idx & 511;
    g_M[idx] = ((d == e) ? 1.f : 0.f) + A[idx] - A[(size_t)e * 512 + d];
}

// ---------------- recurrence (round-11 layout: 2 kernels, 63 launches) -------
__global__ void chunk_scores(int i) {
    const int b = blockIdx.y;
    const int w = threadIdx.x >> 5, lane = threadIdx.x & 31;
    const int c = blockIdx.x * 8 + w;
    const float* krow = g_k + ((size_t)(b * Tt + i * 64 + c)) * 512;
    const float* hb = g_hist + (size_t)b * 32 * 512;
    __shared__ float sS[8][32];

    for (int j = 0; j < i; j += 2) {
        bool has1 = (j + 1 < i);
        const float* h0 = hb + (size_t)j * 512;
        const float* h1 = hb + (size_t)(j + 1) * 512;
        float a0 = 0.f, a1 = 0.f;
        for (int d = lane * 4; d < 512; d += 128) {
            float4 kv = *(const float4*)&krow[d];
            float4 v0 = *(const float4*)&h0[d];
            a0 += kv.x * v0.x + kv.y * v0.y + kv.z * v0.z + kv.w * v0.w;
            if (has1) {
                float4 v1 = *(const float4*)&h1[d];
                a1 += kv.x * v1.x + kv.y * v1.y + kv.z * v1.z + kv.w * v1.w;
            }
        }
        #pragma unroll
        for (int o = 16; o > 0; o >>= 1) {
            a0 += __shfl_xor_sync(0xffffffffu, a0, o);
            a1 += __shfl_xor_sync(0xffffffffu, a1, o);
        }
        if (lane == 0) {
            sS[w][j] = a0 * SCALE;
            if (has1) sS[w][j + 1] = a1 * SCALE;
        }
    }
    __syncwarp();
    float v = (lane < i) ? sS[w][lane] : -1e30f;
    float mx = v;
    #pragma unroll
    for (int o = 16; o > 0; o >>= 1) mx = fmaxf(mx, __shfl_xor_sync(0xffffffffu, mx, o));
    float e = (lane < i) ? __expf(v - mx) : 0.f;
    float s = e;
    #pragma unroll
    for (int o = 16; o > 0; o >>= 1) s += __shfl_xor_sync(0xffffffffu, s, o);
    if (lane < i) g_W[((size_t)b * 64 + c) * 32 + lane] = e / s;
}

__global__ void chunk_qout(int i) {
    const int b = blockIdx.y;
    const int d = blockIdx.x * 128 + threadIdx.x;
    __shared__ float sw[64][32];
    if (i > 0) {
        for (int idx = threadIdx.x; idx < 64 * 32; idx += 128)
            sw[idx >> 5][idx & 31] = g_W[(size_t)b * 2048 + idx];
        __syncthreads();
    }
    float qi_[64];
    #pragma unroll
    for (int c = 0; c < 64; c++) qi_[c] = 0.f;
    float base = 0.f;
    if (i > 0) {
        base = g_hist[((size_t)(b * 32 + i - 1)) * 512 + d];
        for (int j = 0; j < i; j++) {
            float h = g_hist[((size_t)(b * 32 + j)) * 512 + d];
            #pragma unroll
            for (int c = 0; c < 64; c++) qi_[c] += sw[c][j] * h;
        }
    }
    const size_t rb = ((size_t)(b * Tt + i * 64)) * 512 + d;
    float run = 0.f, val = 0.f;
    #pragma unroll
    for (int c = 0; c < 64; c++) {
        size_t idx = rb + (size_t)c * 512;
        run += g_g[idx] * g_q[idx];
        val = run + ((i > 0) ? (base + qi_[c]) : 0.f);
        g_Qc[idx] = val;
    }
    g_hist[((size_t)(b * 32 + i)) * 512 + d] = val;
}

// ---------------- norm + rope (unchanged) ----------------
__global__ void norm_rope() {
    const size_t row = blockIdx.x;
    const int tpos = (int)(row & 2047);
    const float* qc = g_Qc + row * 512;
    const float* kr = g_k + row * 512;
    __shared__ float red[8][4];
    __shared__ float stats[2];
    const int t = threadIdx.x;
    const int w = t >> 5, lane = t & 31;

    float a0 = qc[t], a1 = qc[t + 256];
    float c0 = kr[t], c1 = kr[t + 256];
    float sq = a0 + a1, sq2 = a0 * a0 + a1 * a1;
    float sk = c0 + c1, sk2 = c0 * c0 + c1 * c1;
    #pragma unroll
    for (int o = 16; o > 0; o >>= 1) {
        sq  += __shfl_xor_sync(0xffffffffu, sq,  o);
        sq2 += __shfl_xor_sync(0xffffffffu, sq2, o);
        sk  += __shfl_xor_sync(0xffffffffu, sk,  o);
        sk2 += __shfl_xor_sync(0xffffffffu, sk2, o);
    }
    if (lane == 0) { red[w][0] = sq; red[w][1] = sq2; red[w][2] = sk; red[w][3] = sk2; }
    __syncthreads();
    if (t == 0) {
        float A = 0, B2 = 0, C3 = 0, D4 = 0;
        #pragma unroll
        for (int ww = 0; ww < 8; ww++) {
            A += red[ww][0]; B2 += red[ww][1]; C3 += red[ww][2]; D4 += red[ww][3];
        }
        float mq = A / 512.f, mk = C3 / 512.f;
        float vq = (B2 - 512.f * mq * mq) / 511.f;
        float vk = (D4 - 512.f * mk * mk) / 511.f;
        float std_s = 0.5f * (sqrtf(fmaxf(vq, 0.f)) + sqrtf(fmaxf(vk, 0.f)));
        stats[0] = 0.5f * (mq + mk);
        stats[1] = 1.f / (std_s + 1e-6f);
    }
    __syncthreads();
    const float mean = stats[0], inv = stats[1];
    const float cs = g_cos[tpos * 256 + t];
    const float sn = g_sin[tpos * 256 + t];
    float q1 = (qc[2 * t]     - mean) * inv;
    float q2 = (qc[2 * t + 1] - mean) * inv;
    float k1 = (kr[2 * t]     - mean) * inv;
    float k2 = (kr[2 * t + 1] - mean) * inv;
    g_Qr[row * 512 + t]       = q1 * cs - q2 * sn;
    g_Qr[row * 512 + t + 256] = q1 * sn + q2 * cs;
    g_Kr[row * 512 + t]       = k1 * cs - k2 * sn;
    g_Kr[row * 512 + t + 256] = k1 * sn + k2 * cs;
}

// ---------------- Flash attention: Bq=Bk=64, 256 threads, acc in shared.
// QK^T in DOT-PRODUCT form with row-major staging (no transpose scatter).
// ----------------
constexpr int FSTR = 516;               // sAcc row stride (floats)
constexpr int FQ   = 64 * FSTR;         // 33024
constexpr int FK   = FQ + 64 * 68;      // sQ  at [FQ, FK)   (row-major now)
constexpr int FS   = FK + 64 * 68;      // sK  at [FK, FS)
constexpr int FM   = FS + 64 * 68;      // sSt at [FS, FM)
constexpr int FL   = FM + 64;
constexpr int FA   = FL + 64;
constexpr int FTOT = FA + 64;           // 46272 floats = 185088 bytes

__global__ void flash_kernel(const float* __restrict__ sinkp,
                             const float* __restrict__ vnull,
                             float* __restrict__ out) {
    extern __shared__ float sh[];
    float* sAcc = sh;
    float* sQ   = sh + FQ;   // [r][68] row-major Q d-chunk
    float* sK   = sh + FK;   // [r][68] row-major K d-chunk / V chunk (PV phase)
    float* sSt  = sh + FS;   // [c][68] scores^T -> probs^T
    float* sM   = sh + FM;
    float* sL   = sh + FL;
    float* sAl  = sh + FA;

    const int t  = threadIdx.x;
    const int tq = t >> 4, tk = t & 15;
    const int qi = 31 - (blockIdx.x >> 3);   // heavy tiles first (LPT)
    const int b  = blockIdx.x & 7;
    const int q0 = qi * 64;
    const size_t bT = (size_t)b * Tt;
    const int sr  = t >> 2;                  // staging row 0..63
    const int sb4 = (t & 3) << 4;            // staging col base (0,16,32,48)
    const int srow = t >> 4;                 // V staging row 0..15
    const int sc4  = (t & 15) << 2;          // V staging col*4

    for (int f4 = t; f4 < FQ / 4; f4 += 256)
        ((float4*)sAcc)[f4] = make_float4(0.f, 0.f, 0.f, 0.f);
    if (t < 64) { sM[t] = -1e30f; sL[t] = 0.f; }
    __syncthreads();

    for (int kb = 0; kb <= qi; kb++) {
        const int k0 = kb * 64;
        float sc[4][4] = {};
        // ---- S = Q K^T over d in chunks of 64 (row-major, dot-product) ----
        for (int dc = 0; dc < 512; dc += 64) {
            #pragma unroll
            for (int m = 0; m < 4; m++) {
                int c4 = sb4 + (m << 2);
                *(float4*)&sQ[sr * 68 + c4] =
                    *(const float4*)&g_Qg[(bT + q0 + sr) * 512 + dc + c4];
                *(float4*)&sK[sr * 68 + c4] =
                    *(const float4*)&g_Kg[(bT + k0 + sr) * 512 + dc + c4];
            }
            __syncthreads();
            #pragma unroll 4
            for (int d4 = 0; d4 < 64; d4 += 4) {
                float4 qa[4], kbv[4];
                #pragma unroll
                for (int i = 0; i < 4; i++)
                    qa[i] = *(const float4*)&sQ[((tq << 2) + i) * 68 + d4];
                #pragma unroll
                for (int j = 0; j < 4; j++)
                    kbv[j] = *(const float4*)&sK[((tk << 2) + j) * 68 + d4];
                #pragma unroll
                for (int i = 0; i < 4; i++)
                    #pragma unroll
                    for (int j = 0; j < 4; j++)
                        sc[i][j] += qa[i].x * kbv[j].x + qa[i].y * kbv[j].y
                                  + qa[i].z * kbv[j].z + qa[i].w * kbv[j].w;
            }
            __syncthreads();
        }
        // ---- store S^T with scale + causal mask on diagonal block ----
        const bool diag = (kb == qi);
        #pragma unroll
        for (int i = 0; i < 4; i++) {
            int r = (tq << 2) + i;
            #pragma unroll
            for (int j = 0; j < 4; j++) {
                int c = (tk << 2) + j;
                float s = sc[i][j] * SCALE;
                if (diag && c > r) s = -1e30f;
                sSt[c * 68 + r] = s;
            }
        }
        __syncthreads();
        // ---- online softmax: 4 threads per row ----
        {
            int r = t >> 2, sub = t & 3;
            float mx = -1e30f;
            for (int c = sub; c < 64; c += 4) mx = fmaxf(mx, sSt[c * 68 + r]);
            mx = fmaxf(mx, __shfl_xor_sync(0xffffffffu, mx, 1));
            mx = fmaxf(mx, __shfl_xor_sync(0xffffffffu, mx, 2));
            float mold = sM[r];
            float mnew = fmaxf(mold, mx);
            float ls = 0.f;
            for (int c = sub; c < 64; c += 4) {
                float e = __expf(sSt[c * 68 + r] - mnew);
                sSt[c * 68 + r] = e;
                ls += e;
            }
            ls += __shfl_xor_sync(0xffffffffu, ls, 1);
            ls += __shfl_xor_sync(0xffffffffu, ls, 2);
            if (sub == 0) {
                float al = __expf(mold - mnew);
                sAl[r] = al;
                sM[r] = mnew;
                sL[r] = sL[r] * al + ls;
            }
        }
        __syncthreads();
        // ---- O = al*O + P V, d-chunked; V staged row-major into sK ----
        for (int dc = 0; dc < 512; dc += 64) {
            #pragma unroll
            for (int rr = 0; rr < 4; rr++) {
                int r = srow + rr * 16;
                *(float4*)&sK[r * 68 + sc4] =
                    *(const float4*)&g_v[(bT + k0 + r) * 512 + dc + sc4];
            }
            __syncthreads();
            float o[4][4] = {};
            #pragma unroll
            for (int s = 0; s < 64; s++) {
                float4 p4 = *(const float4*)&sSt[s * 68 + (tq << 2)];
                float4 v4 = *(const float4*)&sK[s * 68 + (tk << 2)];
                float pv[4] = {p4.x, p4.y, p4.z, p4.w};
                float vv[4] = {v4.x, v4.y, v4.z, v4.w};
                #pragma unroll
                for (int i = 0; i < 4; i++)
                    #pragma unroll
                    for (int j = 0; j < 4; j++)
                        o[i][j] += pv[i] * vv[j];
            }
            #pragma unroll
            for (int i = 0; i < 4; i++) {
                int r = (tq << 2) + i;
                float al = sAl[r];
                float4* ap = (float4*)&sAcc[r * FSTR + dc + (tk << 2)];
                float4 a = *ap;
                a.x = a.x * al + o[i][0];
                a.y = a.y * al + o[i][1];
                a.z = a.z * al + o[i][2];
                a.w = a.w * al + o[i][3];
                *ap = a;
            }
            __syncthreads();
        }
    }
    // ---- epilogue: fold the sink logit, normalize, write ----
    {
        float skv = *sinkp;
        int r = t >> 2, sub = t & 3;
        float m = sM[r], l = sL[r];
        float M2 = fmaxf(m, skv);
        float em = __expf(m - M2);
        float es = __expf(skv - M2);
        float inv = 1.f / (l * em + es);
        size_t ob = (bT + q0 + r) * (size_t)512;
        for (int d = sub * 128; d < sub * 128 + 128; d += 4) {
            float4 a = *(float4*)&sAcc[r * FSTR + d];
            float4 vn = *(const float4*)&vnull[d];
            float4 o;
            o.x = (a.x * em + es * vn.x) * inv;
            o.y = (a.y * em + es * vn.y) * inv;
            o.z = (a.z * em + es * vn.z) * inv;
            o.w = (a.w * em + es * vn.w) * inv;
            *(float4*)&out[ob + d] = o;
        }
    }
}

// ---------------- launch ----------------
extern "C" void kernel_launch(void* const* d_in, const int* in_sizes, int n_in,
                              void* d_out, int out_size) {
    const float* x     = (const float*)d_in[0];
    const float* Wq    = (const float*)d_in[1];
    const float* Wk    = (const float*)d_in[2];
    const float* Wv    = (const float*)d_in[3];
    const float* Wg    = (const float*)d_in[4];
    const float* bg    = (const float*)d_in[5];
    const float* A     = (const float*)d_in[6];
    const float* sink  = (const float*)d_in[7];
    const float* vnull = (const float*)d_in[8];
    float* out = (float*)d_out;

    cudaFuncSetAttribute(flash_kernel,
                         cudaFuncAttributeMaxDynamicSharedMemorySize,
                         FTOT * (int)sizeof(float));

    dim3 gg(8, 256);
    gemm64<0, 1, 0><<<gg, 256>>>(x, Wq, nullptr);
    gemm64<0, 1, 1><<<gg, 256>>>(x, Wk, nullptr);
    gemm64<0, 1, 2><<<gg, 256>>>(x, Wv, nullptr);
    gemm64<1, 1, 3><<<gg, 256>>>(x, Wg, bg);

    rope_table<<<2048, 256>>>();
    build_M<<<1024, 256>>>(A);

    chunk_qout<<<dim3(4, 8), 128>>>(0);
    for (int i = 1; i < 32; i++) {
        chunk_scores<<<dim3(8, 8), 256>>>(i);
        chunk_qout<<<dim3(4, 8), 128>>>(i);
    }

    norm_rope<<<16384, 256>>>();

    gemm64<0, 0, 4><<<gg, 256>>>(nullptr, nullptr, nullptr);  // Qg = Qr @ M
    gemm64<0, 0, 5><<<gg, 256>>>(nullptr, nullptr, nullptr);  // Kg = Kr @ M

    flash_kernel<<<256, 256, FTOT * (int)sizeof(float)>>>(sink, vnull, out);
}

// round 15
// speedup vs baseline: 1.1884x; 1.1884x over previous
#include <cuda_runtime.h>
#include <math.h>

constexpr int Tt  = 2048;
constexpr int DHd = 512;
constexpr int NT  = 8 * 2048;
constexpr float SCALE = 0.044194173824159216f; // 512^-0.5

__device__ float g_q [NT * DHd];
__device__ float g_k [NT * DHd];
__device__ float g_v [NT * DHd];
__device__ float g_g [NT * DHd];
__device__ float g_Qc[NT * DHd];
__device__ float g_Qr[NT * DHd];
__device__ float g_Kr[NT * DHd];
__device__ float g_Qg[NT * DHd];
__device__ float g_Kg[NT * DHd];
__device__ float g_M [DHd * DHd];
__device__ float g_hist[8 * 32 * DHd];
__device__ float g_W [8 * 64 * 32];
__device__ float g_cos[Tt * 256];
__device__ float g_sin[Tt * 256];

// ---------------- GEMM (unchanged, at fp32 FFMA ceiling) ----------------
template<int MODE, int TRANSB, int SEL>
__global__ void gemm64(const float* __restrict__ Ain,
                       const float* __restrict__ Bin,
                       const float* __restrict__ bias) {
    const float* A;
    float* C;
    if constexpr (SEL == 0)      { A = Ain;  C = g_q;  }
    else if constexpr (SEL == 1) { A = Ain;  C = g_k;  }
    else if constexpr (SEL == 2) { A = Ain;  C = g_v;  }
    else if constexpr (SEL == 3) { A = Ain;  C = g_g;  }
    else if constexpr (SEL == 4) { A = g_Qr; C = g_Qg; }
    else                         { A = g_Kr; C = g_Kg; }
    const float* Bm = (SEL >= 4) ? (const float*)g_M : Bin;

    constexpr int K = 512, N = 512;
    __shared__ float As[16][68];
    __shared__ float Bs[16][68];
    const int t  = threadIdx.x;
    const int tx = t & 15, ty = t >> 4;
    const int n0 = blockIdx.x * 64, m0 = blockIdx.y * 64;
    const int ar = t >> 2, ac = (t & 3) << 2;
    float acc[4][4] = {};

    for (int k0 = 0; k0 < K; k0 += 16) {
        float4 va = *(const float4*)&A[(size_t)(m0 + ar) * K + k0 + ac];
        As[ac + 0][ar] = va.x; As[ac + 1][ar] = va.y;
        As[ac + 2][ar] = va.z; As[ac + 3][ar] = va.w;
        if constexpr (TRANSB) {
            float4 vb = *(const float4*)&Bm[(size_t)(n0 + ar) * K + k0 + ac];
            Bs[ac + 0][ar] = vb.x; Bs[ac + 1][ar] = vb.y;
            Bs[ac + 2][ar] = vb.z; Bs[ac + 3][ar] = vb.w;
        } else {
            *(float4*)&Bs[ty][tx << 2] =
                *(const float4*)&Bm[(size_t)(k0 + ty) * N + n0 + (tx << 2)];
        }
        __syncthreads();
        #pragma unroll
        for (int kk = 0; kk < 16; kk++) {
            float4 a4 = *(const float4*)&As[kk][ty << 2];
            float4 b4 = *(const float4*)&Bs[kk][tx << 2];
            float av[4] = {a4.x, a4.y, a4.z, a4.w};
            float bv[4] = {b4.x, b4.y, b4.z, b4.w};
            #pragma unroll
            for (int i = 0; i < 4; i++)
                #pragma unroll
                for (int j = 0; j < 4; j++)
                    acc[i][j] += av[i] * bv[j];
        }
        __syncthreads();
    }
    #pragma unroll
    for (int i = 0; i < 4; i++) {
        size_t rowb = (size_t)(m0 + (ty << 2) + i) * N;
        #pragma unroll
        for (int j = 0; j < 4; j++) {
            int n = n0 + (tx << 2) + j;
            float v = acc[i][j];
            if constexpr (MODE == 1) v = 1.f / (1.f + __expf(-(v + bias[n])));
            C[rowb + n] = v;
        }
    }
}

__global__ void rope_table() {
    int tp = blockIdx.x, p = threadIdx.x;
    double invf = pow(10000.0, -((double)(2 * p)) / 512.0);
    float ang = (float)tp * (float)invf;
    g_cos[tp * 256 + p] = (float)cos((double)ang);
    g_sin[tp * 256 + p] = (float)sin((double)ang);
}

__global__ void build_M(const float* __restrict__ A) {
    int idx = blockIdx.x * 256 + threadIdx.x;
    int d = idx >> 9, e = idx & 511;
    g_M[idx] = ((d == e) ? 1.f : 0.f) + A[idx] - A[(size_t)e * 512 + d];
}

// ---------------- recurrence (round-11 layout: 2 kernels, 63 launches) -------
__global__ void chunk_scores(int i) {
    const int b = blockIdx.y;
    const int w = threadIdx.x >> 5, lane = threadIdx.x & 31;
    const int c = blockIdx.x * 8 + w;
    const float* krow = g_k + ((size_t)(b * Tt + i * 64 + c)) * 512;
    const float* hb = g_hist + (size_t)b * 32 * 512;
    __shared__ float sS[8][32];

    for (int j = 0; j < i; j += 2) {
        bool has1 = (j + 1 < i);
        const float* h0 = hb + (size_t)j * 512;
        const float* h1 = hb + (size_t)(j + 1) * 512;
        float a0 = 0.f, a1 = 0.f;
        for (int d = lane * 4; d < 512; d += 128) {
            float4 kv = *(const float4*)&krow[d];
            float4 v0 = *(const float4*)&h0[d];
            a0 += kv.x * v0.x + kv.y * v0.y + kv.z * v0.z + kv.w * v0.w;
            if (has1) {
                float4 v1 = *(const float4*)&h1[d];
                a1 += kv.x * v1.x + kv.y * v1.y + kv.z * v1.z + kv.w * v1.w;
            }
        }
        #pragma unroll
        for (int o = 16; o > 0; o >>= 1) {
            a0 += __shfl_xor_sync(0xffffffffu, a0, o);
            a1 += __shfl_xor_sync(0xffffffffu, a1, o);
        }
        if (lane == 0) {
            sS[w][j] = a0 * SCALE;
            if (has1) sS[w][j + 1] = a1 * SCALE;
        }
    }
    __syncwarp();
    float v = (lane < i) ? sS[w][lane] : -1e30f;
    float mx = v;
    #pragma unroll
    for (int o = 16; o > 0; o >>= 1) mx = fmaxf(mx, __shfl_xor_sync(0xffffffffu, mx, o));
    float e = (lane < i) ? __expf(v - mx) : 0.f;
    float s = e;
    #pragma unroll
    for (int o = 16; o > 0; o >>= 1) s += __shfl_xor_sync(0xffffffffu, s, o);
    if (lane < i) g_W[((size_t)b * 64 + c) * 32 + lane] = e / s;
}

__global__ void chunk_qout(int i) {
    const int b = blockIdx.y;
    const int d = blockIdx.x * 128 + threadIdx.x;
    __shared__ float sw[64][32];
    if (i > 0) {
        for (int idx = threadIdx.x; idx < 64 * 32; idx += 128)
            sw[idx >> 5][idx & 31] = g_W[(size_t)b * 2048 + idx];
        __syncthreads();
    }
    float qi_[64];
    #pragma unroll
    for (int c = 0; c < 64; c++) qi_[c] = 0.f;
    float base = 0.f;
    if (i > 0) {
        base = g_hist[((size_t)(b * 32 + i - 1)) * 512 + d];
        for (int j = 0; j < i; j++) {
            float h = g_hist[((size_t)(b * 32 + j)) * 512 + d];
            #pragma unroll
            for (int c = 0; c < 64; c++) qi_[c] += sw[c][j] * h;
        }
    }
    const size_t rb = ((size_t)(b * Tt + i * 64)) * 512 + d;
    float run = 0.f, val = 0.f;
    #pragma unroll
    for (int c = 0; c < 64; c++) {
        size_t idx = rb + (size_t)c * 512;
        run += g_g[idx] * g_q[idx];
        val = run + ((i > 0) ? (base + qi_[c]) : 0.f);
        g_Qc[idx] = val;
    }
    g_hist[((size_t)(b * 32 + i)) * 512 + d] = val;
}

// ---------------- norm + rope (unchanged) ----------------
__global__ void norm_rope() {
    const size_t row = blockIdx.x;
    const int tpos = (int)(row & 2047);
    const float* qc = g_Qc + row * 512;
    const float* kr = g_k + row * 512;
    __shared__ float red[8][4];
    __shared__ float stats[2];
    const int t = threadIdx.x;
    const int w = t >> 5, lane = t & 31;

    float a0 = qc[t], a1 = qc[t + 256];
    float c0 = kr[t], c1 = kr[t + 256];
    float sq = a0 + a1, sq2 = a0 * a0 + a1 * a1;
    float sk = c0 + c1, sk2 = c0 * c0 + c1 * c1;
    #pragma unroll
    for (int o = 16; o > 0; o >>= 1) {
        sq  += __shfl_xor_sync(0xffffffffu, sq,  o);
        sq2 += __shfl_xor_sync(0xffffffffu, sq2, o);
        sk  += __shfl_xor_sync(0xffffffffu, sk,  o);
        sk2 += __shfl_xor_sync(0xffffffffu, sk2, o);
    }
    if (lane == 0) { red[w][0] = sq; red[w][1] = sq2; red[w][2] = sk; red[w][3] = sk2; }
    __syncthreads();
    if (t == 0) {
        float A = 0, B2 = 0, C3 = 0, D4 = 0;
        #pragma unroll
        for (int ww = 0; ww < 8; ww++) {
            A += red[ww][0]; B2 += red[ww][1]; C3 += red[ww][2]; D4 += red[ww][3];
        }
        float mq = A / 512.f, mk = C3 / 512.f;
        float vq = (B2 - 512.f * mq * mq) / 511.f;
        float vk = (D4 - 512.f * mk * mk) / 511.f;
        float std_s = 0.5f * (sqrtf(fmaxf(vq, 0.f)) + sqrtf(fmaxf(vk, 0.f)));
        stats[0] = 0.5f * (mq + mk);
        stats[1] = 1.f / (std_s + 1e-6f);
    }
    __syncthreads();
    const float mean = stats[0], inv = stats[1];
    const float cs = g_cos[tpos * 256 + t];
    const float sn = g_sin[tpos * 256 + t];
    float q1 = (qc[2 * t]     - mean) * inv;
    float q2 = (qc[2 * t + 1] - mean) * inv;
    float k1 = (kr[2 * t]     - mean) * inv;
    float k2 = (kr[2 * t + 1] - mean) * inv;
    g_Qr[row * 512 + t]       = q1 * cs - q2 * sn;
    g_Qr[row * 512 + t + 256] = q1 * sn + q2 * cs;
    g_Kr[row * 512 + t]       = k1 * cs - k2 * sn;
    g_Kr[row * 512 + t + 256] = k1 * sn + k2 * cs;
}

// ---------------- Flash attention: round-11 structure + XOR bank swizzle
// on the r-group of all transposed tiles (sQt/sKt/sSt).
// Element (dd, r) -> dd*68 + (((r>>2) ^ (dd&15) ^ (dd>>4)) & 15)*4 + (r&3).
// ----------------
__device__ __forceinline__ int swz(int dd, int rgrp) {
    return dd * 68 + ((((rgrp) ^ (dd & 15) ^ (dd >> 4)) & 15) << 2);
}

constexpr int FSTR = 516;               // sAcc row stride (floats)
constexpr int FQ   = 64 * FSTR;         // 33024
constexpr int FK   = FQ + 64 * 68;      // sQt
constexpr int FS   = FK + 64 * 68;      // sKt
constexpr int FM   = FS + 64 * 68;      // sSt
constexpr int FL   = FM + 64;
constexpr int FA   = FL + 64;
constexpr int FTOT = FA + 64;           // 46272 floats = 185088 bytes

__global__ __launch_bounds__(256)
void flash_kernel(const float* __restrict__ sinkp,
                  const float* __restrict__ vnull,
                  float* __restrict__ out) {
    extern __shared__ float sh[];
    float* sAcc = sh;
    float* sQt  = sh + FQ;   // [dd][r] swizzled transposed Q d-chunk
    float* sKt  = sh + FK;   // [dd][r] swizzled transposed K d-chunk / V rows (PV)
    float* sSt  = sh + FS;   // [c][r] swizzled scores^T -> probs^T
    float* sM   = sh + FM;
    float* sL   = sh + FL;
    float* sAl  = sh + FA;

    const int t  = threadIdx.x;
    const int tq = t >> 4, tk = t & 15;
    const int qi = 31 - (blockIdx.x >> 3);   // heavy tiles first (LPT)
    const int b  = blockIdx.x & 7;
    const int q0 = qi * 64;
    const size_t bT = (size_t)b * Tt;
    const int srow = t >> 4;                 // staging row 0..15
    const int sc4  = (t & 15) << 2;          // staging col*4

    for (int f4 = t; f4 < FQ / 4; f4 += 256)
        ((float4*)sAcc)[f4] = make_float4(0.f, 0.f, 0.f, 0.f);
    if (t < 64) { sM[t] = -1e30f; sL[t] = 0.f; }
    __syncthreads();

    for (int kb = 0; kb <= qi; kb++) {
        const int k0 = kb * 64;
        float sc[4][4] = {};
        // ---- S = Q K^T over d in chunks of 64 (swizzled transposed staging) ----
        for (int dc = 0; dc < 512; dc += 64) {
            #pragma unroll
            for (int rr = 0; rr < 4; rr++) {
                int r = srow + rr * 16;
                int rg = r >> 2, rb = r & 3;
                float4 qv = *(const float4*)&g_Qg[(bT + q0 + r) * 512 + dc + sc4];
                sQt[swz(sc4 + 0, rg) + rb] = qv.x;
                sQt[swz(sc4 + 1, rg) + rb] = qv.y;
                sQt[swz(sc4 + 2, rg) + rb] = qv.z;
                sQt[swz(sc4 + 3, rg) + rb] = qv.w;
                float4 kv = *(const float4*)&g_Kg[(bT + k0 + r) * 512 + dc + sc4];
                sKt[swz(sc4 + 0, rg) + rb] = kv.x;
                sKt[swz(sc4 + 1, rg) + rb] = kv.y;
                sKt[swz(sc4 + 2, rg) + rb] = kv.z;
                sKt[swz(sc4 + 3, rg) + rb] = kv.w;
            }
            __syncthreads();
            #pragma unroll
            for (int dd = 0; dd < 64; dd++) {
                float4 a4 = *(const float4*)&sQt[swz(dd, tq)];
                float4 b4 = *(const float4*)&sKt[swz(dd, tk)];
                float av[4] = {a4.x, a4.y, a4.z, a4.w};
                float bv[4] = {b4.x, b4.y, b4.z, b4.w};
                #pragma unroll
                for (int i = 0; i < 4; i++)
                    #pragma unroll
                    for (int j = 0; j < 4; j++)
                        sc[i][j] += av[i] * bv[j];
            }
            __syncthreads();
        }
        // ---- store S^T (swizzled) with scale + causal mask on diagonal ----
        const bool diag = (kb == qi);
        #pragma unroll
        for (int i = 0; i < 4; i++) {
            int r = (tq << 2) + i;
            #pragma unroll
            for (int j = 0; j < 4; j++) {
                int c = (tk << 2) + j;
                float s = sc[i][j] * SCALE;
                if (diag && c > r) s = -1e30f;
                sSt[swz(c, tq) + i] = s;
            }
        }
        __syncthreads();
        // ---- online softmax: 4 threads per row ----
        {
            int r = t >> 2, sub = t & 3;
            int rg = r >> 2, rb = r & 3;
            float mx = -1e30f;
            for (int c = sub; c < 64; c += 4) mx = fmaxf(mx, sSt[swz(c, rg) + rb]);
            mx = fmaxf(mx, __shfl_xor_sync(0xffffffffu, mx, 1));
            mx = fmaxf(mx, __shfl_xor_sync(0xffffffffu, mx, 2));
            float mold = sM[r];
            float mnew = fmaxf(mold, mx);
            float ls = 0.f;
            for (int c = sub; c < 64; c += 4) {
                float e = __expf(sSt[swz(c, rg) + rb] - mnew);
                sSt[swz(c, rg) + rb] = e;
                ls += e;
            }
            ls += __shfl_xor_sync(0xffffffffu, ls, 1);
            ls += __shfl_xor_sync(0xffffffffu, ls, 2);
            if (sub == 0) {
                float al = __expf(mold - mnew);
                sAl[r] = al;
                sM[r] = mnew;
                sL[r] = sL[r] * al + ls;
            }
        }
        __syncthreads();
        // ---- O = al*O + P V, d-chunked; V staged row-major into sKt ----
        for (int dc = 0; dc < 512; dc += 64) {
            #pragma unroll
            for (int rr = 0; rr < 4; rr++) {
                int r = srow + rr * 16;
                *(float4*)&sKt[r * 68 + sc4] =
                    *(const float4*)&g_v[(bT + k0 + r) * 512 + dc + sc4];
            }
            __syncthreads();
            float o[4][4] = {};
            #pragma unroll
            for (int s = 0; s < 64; s++) {
                float4 p4 = *(const float4*)&sSt[swz(s, tq)];
                float4 v4 = *(const float4*)&sKt[s * 68 + (tk << 2)];
                float pv[4] = {p4.x, p4.y, p4.z, p4.w};
                float vv[4] = {v4.x, v4.y, v4.z, v4.w};
                #pragma unroll
                for (int i = 0; i < 4; i++)
                    #pragma unroll
                    for (int j = 0; j < 4; j++)
                        o[i][j] += pv[i] * vv[j];
            }
            #pragma unroll
            for (int i = 0; i < 4; i++) {
                int r = (tq << 2) + i;
                float al = sAl[r];
                float4* ap = (float4*)&sAcc[r * FSTR + dc + (tk << 2)];
                float4 a = *ap;
                a.x = a.x * al + o[i][0];
                a.y = a.y * al + o[i][1];
                a.z = a.z * al + o[i][2];
                a.w = a.w * al + o[i][3];
                *ap = a;
            }
            __syncthreads();
        }
    }
    // ---- epilogue: fold the sink logit, normalize, write ----
    {
        float skv = *sinkp;
        int r = t >> 2, sub = t & 3;
        float m = sM[r], l = sL[r];
        float M2 = fmaxf(m, skv);
        float em = __expf(m - M2);
        float es = __expf(skv - M2);
        float inv = 1.f / (l * em + es);
        size_t ob = (bT + q0 + r) * (size_t)512;
        for (int d = sub * 128; d < sub * 128 + 128; d += 4) {
            float4 a = *(float4*)&sAcc[r * FSTR + d];
            float4 vn = *(const float4*)&vnull[d];
            float4 o;
            o.x = (a.x * em + es * vn.x) * inv;
            o.y = (a.y * em + es * vn.y) * inv;
            o.z = (a.z * em + es * vn.z) * inv;
            o.w = (a.w * em + es * vn.w) * inv;
            *(float4*)&out[ob + d] = o;
        }
    }
}

// ---------------- launch ----------------
extern "C" void kernel_launch(void* const* d_in, const int* in_sizes, int n_in,
                              void* d_out, int out_size) {
    const float* x     = (const float*)d_in[0];
    const float* Wq    = (const float*)d_in[1];
    const float* Wk    = (const float*)d_in[2];
    const float* Wv    = (const float*)d_in[3];
    const float* Wg    = (const float*)d_in[4];
    const float* bg    = (const float*)d_in[5];
    const float* A     = (const float*)d_in[6];
    const float* sink  = (const float*)d_in[7];
    const float* vnull = (const float*)d_in[8];
    float* out = (float*)d_out;

    cudaFuncSetAttribute(flash_kernel,
                         cudaFuncAttributeMaxDynamicSharedMemorySize,
                         FTOT * (int)sizeof(float));

    dim3 gg(8, 256);
    gemm64<0, 1, 0><<<gg, 256>>>(x, Wq, nullptr);
    gemm64<0, 1, 1><<<gg, 256>>>(x, Wk, nullptr);
    gemm64<0, 1, 2><<<gg, 256>>>(x, Wv, nullptr);
    gemm64<1, 1, 3><<<gg, 256>>>(x, Wg, bg);

    rope_table<<<2048, 256>>>();
    build_M<<<1024, 256>>>(A);

    chunk_qout<<<dim3(4, 8), 128>>>(0);
    for (int i = 1; i < 32; i++) {
        chunk_scores<<<dim3(8, 8), 256>>>(i);
        chunk_qout<<<dim3(4, 8), 128>>>(i);
    }

    norm_rope<<<16384, 256>>>();

    gemm64<0, 0, 4><<<gg, 256>>>(nullptr, nullptr, nullptr);  // Qg = Qr @ M
    gemm64<0, 0, 5><<<gg, 256>>>(nullptr, nullptr, nullptr);  // Kg = Kr @ M

    flash_kernel<<<256, 256, FTOT * (int)sizeof(float)>>>(sink, vnull, out);
}